// round 2
// baseline (speedup 1.0000x reference)
#include <cuda_runtime.h>

#define EMB 128
#define MAXB 1024
#define NW 8          // warps per block in pooling kernel
#define GPB 8         // graphs per block in output kernel

// Scratch (device globals; no allocation allowed)
__device__ float g_s[MAXB * EMB];      // pooled softmax-weighted x rows
__device__ float g_flag[MAXB];         // 1 if segment non-empty
__device__ float g_W1[EMB * EMB];      // Wv @ Wm_top
__device__ float g_c[EMB];             // bv @ Wm_top

__device__ __forceinline__ int lower_bound_i(const int* __restrict__ a, int n, int v) {
    int lo = 0, hi = n;
    while (lo < hi) {
        int mid = (lo + hi) >> 1;
        if (a[mid] < v) lo = mid + 1; else hi = mid;
    }
    return lo;
}

// ---------------------------------------------------------------------------
// Kernel 1: per-graph exp-weighted pooling of x rows (softmax is shift-
// invariant; gate values are O(5) so no max subtraction needed in fp32).
//   s_b = sum_i exp(gate_i) * x_i / sum_i exp(gate_i)
// grid = B blocks, 256 threads (8 warps). Each warp: 4 rows per iteration.
// ---------------------------------------------------------------------------
__global__ __launch_bounds__(256) void k_pool(
    const float* __restrict__ x, const int* __restrict__ bidx,
    const float* __restrict__ Wg, const float* __restrict__ bg, int N)
{
    int b = blockIdx.x;
    int start = lower_bound_i(bidx, N, b);
    int end   = lower_bound_i(bidx, N, b + 1);

    int lane = threadIdx.x & 31;
    int w    = threadIdx.x >> 5;

    float4 wg  = ((const float4*)Wg)[lane];
    float  bg0 = __ldg(bg);

    float4 acc = make_float4(0.f, 0.f, 0.f, 0.f);
    float denom = 0.f;

    for (int base = start + w * 4; base < end; base += NW * 4) {
        float4 v[4];
        float  p[4];
        bool   ok[4];
        #pragma unroll
        for (int t = 0; t < 4; t++) {
            int r = base + t;
            ok[t] = r < end;                    // warp-uniform
            v[t] = ok[t] ? __ldg(((const float4*)(x + (size_t)r * EMB)) + lane)
                         : make_float4(0.f, 0.f, 0.f, 0.f);
            p[t] = v[t].x * wg.x + v[t].y * wg.y + v[t].z * wg.z + v[t].w * wg.w;
        }
        #pragma unroll
        for (int off = 16; off; off >>= 1) {
            #pragma unroll
            for (int t = 0; t < 4; t++)
                p[t] += __shfl_xor_sync(0xffffffffu, p[t], off);
        }
        #pragma unroll
        for (int t = 0; t < 4; t++) {
            float e = ok[t] ? __expf(p[t] + bg0) : 0.f;
            acc.x += e * v[t].x; acc.y += e * v[t].y;
            acc.z += e * v[t].z; acc.w += e * v[t].w;
            denom += e;
        }
    }

    __shared__ float sm_acc[NW][EMB];
    __shared__ float sm_d[NW];
    ((float4*)sm_acc[w])[lane] = acc;
    if (lane == 0) sm_d[w] = denom;
    __syncthreads();

    if (threadIdx.x < EMB) {
        float s = 0.f, d = 0.f;
        #pragma unroll
        for (int j = 0; j < NW; j++) {
            s += sm_acc[j][threadIdx.x];
            d += sm_d[j];
        }
        g_s[b * EMB + threadIdx.x] = (d > 0.f) ? (s / d) : 0.f;
        if (threadIdx.x == 0) g_flag[b] = (d > 0.f) ? 1.f : 0.f;
    }
}

// ---------------------------------------------------------------------------
// Kernel 0 (tiny, independent of k_pool): W1 = Wv @ Wm_top, c = bv @ Wm_top
//   (s@Wv+bv)@Wm_top == s@W1 + c   — folds the value GEMM into the MLP GEMM.
// grid = 128 blocks (one per W1 row), 128 threads.
// ---------------------------------------------------------------------------
__global__ __launch_bounds__(128) void k_prep(
    const float* __restrict__ Wv, const float* __restrict__ Wm,
    const float* __restrict__ bv)
{
    __shared__ float row[EMB];
    int i = blockIdx.x;
    int j = threadIdx.x;
    row[j] = Wv[i * EMB + j];
    __syncthreads();

    float a = 0.f;
    #pragma unroll 8
    for (int k = 0; k < EMB; k++)
        a += row[k] * __ldg(Wm + k * EMB + j);     // Wm_top = rows [0,128)
    g_W1[i * EMB + j] = a;

    if (i == 0) {
        float c = 0.f;
        #pragma unroll 8
        for (int k = 0; k < EMB; k++)
            c += __ldg(bv + k) * __ldg(Wm + k * EMB + j);
        g_c[j] = c;
    }
}

// ---------------------------------------------------------------------------
// Kernel 2: out = gp + leaky_relu( s@W1 + flag*c + gp@Wm_bot + bm )
// One 1024x128x256 GEMM. grid = B/GPB blocks, 256 threads.
// Single smem staging: combined weights [256,128] (W1 on top, Wm_bot below)
// + per-graph activations [GPB,256] (s then gp).  136 KB dynamic smem.
// ---------------------------------------------------------------------------
extern __shared__ float smem2[];

__global__ __launch_bounds__(256) void k_out(
    const float* __restrict__ gp, const float* __restrict__ Wm,
    const float* __restrict__ bm, float* __restrict__ out)
{
    float* Wsh = smem2;                    // [2*EMB][EMB]
    float* Ash = Wsh + 2 * EMB * EMB;      // [GPB][2*EMB]

    int gbase = blockIdx.x * GPB;
    int tid = threadIdx.x;

    const float4* W1_4 = (const float4*)g_W1;
    const float4* Wb4  = (const float4*)(Wm + EMB * EMB);   // Wm_bot
    float4* Wsh4 = (float4*)Wsh;
    for (int i = tid; i < EMB * EMB / 4; i += 256) Wsh4[i] = W1_4[i];
    for (int i = tid; i < EMB * EMB / 4; i += 256) Wsh4[EMB * EMB / 4 + i] = Wb4[i];

    {
        const float4* s4  = (const float4*)(g_s + (size_t)gbase * EMB);
        const float4* gp4 = (const float4*)(gp  + (size_t)gbase * EMB);
        float4* Ash4 = (float4*)Ash;
        for (int i = tid; i < GPB * EMB / 4; i += 256) {
            int gl = i / (EMB / 4);
            int kk = i - gl * (EMB / 4);
            Ash4[gl * (2 * EMB / 4) + kk]           = s4[i];
            Ash4[gl * (2 * EMB / 4) + EMB / 4 + kk] = gp4[i];
        }
    }
    __syncthreads();

    int j  = tid & 127;
    int gh = tid >> 7;

    float h[4] = {0.f, 0.f, 0.f, 0.f};
    #pragma unroll 4
    for (int k = 0; k < 2 * EMB; k++) {
        float wv = Wsh[k * EMB + j];
        #pragma unroll
        for (int t = 0; t < 4; t++)
            h[t] += Ash[(gh * 4 + t) * 2 * EMB + k] * wv;
    }

    float bmj = __ldg(bm + j);
    float cj  = g_c[j];
    #pragma unroll
    for (int t = 0; t < 4; t++) {
        int gl = gh * 4 + t;
        float hh = h[t] + g_flag[gbase + gl] * cj + bmj;
        float lr = (hh > 0.f) ? hh : 0.01f * hh;
        out[(size_t)(gbase + gl) * EMB + j] = Ash[gl * 2 * EMB + EMB + j] + lr;
    }
}

extern "C" void kernel_launch(void* const* d_in, const int* in_sizes, int n_in,
                              void* d_out, int out_size)
{
    const float* x    = (const float*)d_in[0];
    const float* gp   = (const float*)d_in[1];
    const int*   bidx = (const int*)  d_in[2];
    const float* Wg   = (const float*)d_in[3];
    const float* bg   = (const float*)d_in[4];
    const float* Wv   = (const float*)d_in[5];
    const float* bv   = (const float*)d_in[6];
    const float* Wm   = (const float*)d_in[7];
    const float* bm   = (const float*)d_in[8];
    float* out = (float*)d_out;

    int N = in_sizes[0] / EMB;
    int B = in_sizes[1] / EMB;

    const int smem_bytes = (2 * EMB * EMB + GPB * 2 * EMB) * (int)sizeof(float); // 139264
    static bool attr_set = false;
    if (!attr_set) {
        cudaFuncSetAttribute(k_out, cudaFuncAttributeMaxDynamicSharedMemorySize, smem_bytes);
        attr_set = true;
    }

    k_prep<<<EMB, 128>>>(Wv, Wm, bv);
    k_pool<<<B, 256>>>(x, bidx, Wg, bg, N);
    k_out<<<B / GPB, 256, smem_bytes>>>(gp, Wm, bm, out);
}

// round 3
// speedup vs baseline: 1.2759x; 1.2759x over previous
#include <cuda_runtime.h>

#define EMB 128
#define MAXB 1024
#define NW 8          // warps per block in pooling kernel
#define GPB 8         // graphs per block in output kernel

#define PREP_BLKS 64
#define COPY_BLKS 32
#define PRE_FIXED (PREP_BLKS + COPY_BLKS + 1)   // 97

// Scratch (device globals; no allocation allowed)
__device__ float g_s[MAXB * EMB];          // pooled softmax-weighted x rows
__device__ float g_flag[MAXB];             // 1 if segment non-empty
__device__ float g_Wcat[2 * EMB * EMB];    // rows [0,128)=Wv@Wm_top, [128,256)=Wm_bot
__device__ float g_c[EMB];                 // bv @ Wm_top
__device__ int   g_start[MAXB + 1];        // segment boundaries

// ---------------------------------------------------------------------------
// Kernel 0 (heterogeneous grid, one launch):
//  blocks [0,64):        W1 rows 2b,2b+1  (W1 = Wv @ Wm_top) -> g_Wcat top
//  blocks [64,96):       copy Wm_bot rows 4(b-64).. -> g_Wcat bottom
//  block  96:            g_c = bv @ Wm_top
//  blocks [97, 97+2048): segment boundary scan -> g_start[0..B]
// ---------------------------------------------------------------------------
__global__ __launch_bounds__(256) void k_pre(
    const float* __restrict__ Wv, const float* __restrict__ Wm,
    const float* __restrict__ bv, const int* __restrict__ bidx,
    int N, int B)
{
    int blk = blockIdx.x;
    int tid = threadIdx.x;

    if (blk < PREP_BLKS) {
        __shared__ float av[2 * EMB];
        av[tid] = Wv[blk * (2 * EMB) + tid];     // 2 consecutive Wv rows
        __syncthreads();
        int j  = tid & (EMB - 1);
        int ih = tid >> 7;
        float acc = 0.f;
        #pragma unroll 16
        for (int k = 0; k < EMB; k++)
            acc += av[ih * EMB + k] * __ldg(Wm + k * EMB + j);
        g_Wcat[(blk * 2 + ih) * EMB + j] = acc;
    } else if (blk < PREP_BLKS + COPY_BLKS) {
        int b = blk - PREP_BLKS;
        const float4* src = (const float4*)(Wm + (size_t)(EMB + b * 4) * EMB);
        float4*       dst = (float4*)(g_Wcat + (size_t)(EMB + b * 4) * EMB);
        if (tid < 128) dst[tid] = src[tid];      // 4 rows = 128 float4
    } else if (blk < PRE_FIXED) {
        __shared__ float sb[EMB];
        if (tid < EMB) sb[tid] = bv[tid];
        __syncthreads();
        if (tid < EMB) {
            float acc = 0.f;
            #pragma unroll 16
            for (int k = 0; k < EMB; k++)
                acc += sb[k] * __ldg(Wm + k * EMB + tid);
            g_c[tid] = acc;
        }
    } else {
        int idx = (blk - PRE_FIXED) * 256 + tid;
        if (idx < N) {
            int cur  = bidx[idx];
            int prev = (idx == 0) ? -1 : bidx[idx - 1];
            for (int b = prev + 1; b <= cur; b++) g_start[b] = idx;
            if (idx == N - 1)
                for (int b = cur + 1; b <= B; b++) g_start[b] = N;
        }
    }
}

// ---------------------------------------------------------------------------
// Kernel 1: per-graph exp-weighted pooling of x rows (softmax shift-invariant;
// gates are O(5) so fp32 exp without max subtraction is safe).
//   s_b = sum_i exp(gate_i) * x_i / sum_i exp(gate_i)
// grid = B blocks, 256 threads (8 warps), 4 rows per warp-iteration.
// ---------------------------------------------------------------------------
__global__ __launch_bounds__(256) void k_pool(
    const float* __restrict__ x,
    const float* __restrict__ Wg, const float* __restrict__ bg)
{
    int b = blockIdx.x;
    int start = g_start[b];
    int end   = g_start[b + 1];

    int lane = threadIdx.x & 31;
    int w    = threadIdx.x >> 5;

    float4 wg  = ((const float4*)Wg)[lane];
    float  bg0 = __ldg(bg);

    float4 acc = make_float4(0.f, 0.f, 0.f, 0.f);
    float denom = 0.f;

    for (int base = start + w * 4; base < end; base += NW * 4) {
        float4 v[4];
        float  p[4];
        bool   ok[4];
        #pragma unroll
        for (int t = 0; t < 4; t++) {
            int r = base + t;
            ok[t] = r < end;                    // warp-uniform
            v[t] = ok[t] ? __ldg(((const float4*)(x + (size_t)r * EMB)) + lane)
                         : make_float4(0.f, 0.f, 0.f, 0.f);
            p[t] = v[t].x * wg.x + v[t].y * wg.y + v[t].z * wg.z + v[t].w * wg.w;
        }
        #pragma unroll
        for (int off = 16; off; off >>= 1) {
            #pragma unroll
            for (int t = 0; t < 4; t++)
                p[t] += __shfl_xor_sync(0xffffffffu, p[t], off);
        }
        #pragma unroll
        for (int t = 0; t < 4; t++) {
            float e = ok[t] ? __expf(p[t] + bg0) : 0.f;
            acc.x += e * v[t].x; acc.y += e * v[t].y;
            acc.z += e * v[t].z; acc.w += e * v[t].w;
            denom += e;
        }
    }

    __shared__ float sm_acc[NW][EMB];
    __shared__ float sm_d[NW];
    ((float4*)sm_acc[w])[lane] = acc;
    if (lane == 0) sm_d[w] = denom;
    __syncthreads();

    if (threadIdx.x < EMB) {
        float s = 0.f, d = 0.f;
        #pragma unroll
        for (int j = 0; j < NW; j++) {
            s += sm_acc[j][threadIdx.x];
            d += sm_d[j];
        }
        g_s[b * EMB + threadIdx.x] = (d > 0.f) ? (s / d) : 0.f;
        if (threadIdx.x == 0) g_flag[b] = (d > 0.f) ? 1.f : 0.f;
    }
}

// ---------------------------------------------------------------------------
// Kernel 2: out = gp + leaky_relu( [s, gp] @ g_Wcat + flag*c + bm )
// grid = B/GPB blocks, 256 threads. Weights streamed from L1/L2 (coalesced,
// hot); only activations staged in smem (8 KB). Thread (gh, j): 4 graphs.
// ---------------------------------------------------------------------------
__global__ __launch_bounds__(256) void k_out(
    const float* __restrict__ gp, const float* __restrict__ bm,
    float* __restrict__ out)
{
    __shared__ float Ash[GPB][2 * EMB];    // [g][k]: k<128 = s, k>=128 = gp

    int gbase = blockIdx.x * GPB;
    int tid = threadIdx.x;

    {
        int gl = tid >> 5;                 // 8 graphs x 32 threads
        int kk = tid & 31;                 // 32 float4 per row
        const float4* s4  = (const float4*)(g_s + (size_t)gbase * EMB);
        const float4* gp4 = (const float4*)(gp  + (size_t)gbase * EMB);
        ((float4*)Ash[gl])[kk]      = s4[gl * 32 + kk];
        ((float4*)Ash[gl])[32 + kk] = gp4[gl * 32 + kk];
    }
    __syncthreads();

    int j  = tid & 127;
    int gh = (tid >> 7) * 4;               // graphs gh..gh+3

    float a0 = 0.f, a1 = 0.f, a2 = 0.f, a3 = 0.f;
    #pragma unroll 4
    for (int k = 0; k < 2 * EMB; k += 4) {
        float w0 = __ldg(g_Wcat + (k + 0) * EMB + j);
        float w1 = __ldg(g_Wcat + (k + 1) * EMB + j);
        float w2 = __ldg(g_Wcat + (k + 2) * EMB + j);
        float w3 = __ldg(g_Wcat + (k + 3) * EMB + j);
        float4 q0 = *(const float4*)&Ash[gh + 0][k];
        float4 q1 = *(const float4*)&Ash[gh + 1][k];
        float4 q2 = *(const float4*)&Ash[gh + 2][k];
        float4 q3 = *(const float4*)&Ash[gh + 3][k];
        a0 += q0.x * w0 + q0.y * w1 + q0.z * w2 + q0.w * w3;
        a1 += q1.x * w0 + q1.y * w1 + q1.z * w2 + q1.w * w3;
        a2 += q2.x * w0 + q2.y * w1 + q2.z * w2 + q2.w * w3;
        a3 += q3.x * w0 + q3.y * w1 + q3.z * w2 + q3.w * w3;
    }

    float bmj = __ldg(bm + j);
    float cj  = g_c[j];
    float hv[4] = {a0, a1, a2, a3};
    #pragma unroll
    for (int t = 0; t < 4; t++) {
        int gl = gh + t;
        float hh = hv[t] + g_flag[gbase + gl] * cj + bmj;
        float lr = (hh > 0.f) ? hh : 0.01f * hh;
        out[(size_t)(gbase + gl) * EMB + j] = Ash[gl][EMB + j] + lr;
    }
}

extern "C" void kernel_launch(void* const* d_in, const int* in_sizes, int n_in,
                              void* d_out, int out_size)
{
    const float* x    = (const float*)d_in[0];
    const float* gp   = (const float*)d_in[1];
    const int*   bidx = (const int*)  d_in[2];
    const float* Wg   = (const float*)d_in[3];
    const float* bg   = (const float*)d_in[4];
    const float* Wv   = (const float*)d_in[5];
    const float* bv   = (const float*)d_in[6];
    const float* Wm   = (const float*)d_in[7];
    const float* bm   = (const float*)d_in[8];
    float* out = (float*)d_out;

    int N = in_sizes[0] / EMB;
    int B = in_sizes[1] / EMB;

    int pre_grid = PRE_FIXED + (N + 255) / 256;
    k_pre<<<pre_grid, 256>>>(Wv, Wm, bv, bidx, N, B);
    k_pool<<<B, 256>>>(x, Wg, bg);
    k_out<<<B / GPB, 256>>>(gp, bm, out);
}

// round 4
// speedup vs baseline: 1.3892x; 1.0888x over previous
#include <cuda_runtime.h>

#define EMB 128
#define MAXB 1024
#define NW 8            // warps per pool block
#define SPLIT 2         // pool blocks per graph
#define GPB 8           // graphs per k_out block
#define PREPB 65        // 64 W1 blocks + 1 c block, fused ahead of pool

// Scratch (device globals; no allocation allowed)
__device__ float g_num[MAXB * SPLIT * EMB];   // partial exp-weighted sums
__device__ float g_den[MAXB * SPLIT];         // partial exp sums
__device__ float g_W1[EMB * EMB];             // Wv @ Wm_top
__device__ float g_c[EMB];                    // bv @ Wm_top
__device__ int   g_start[MAXB + 1];           // segment boundaries

// ---------------------------------------------------------------------------
// Kernel 0: segment boundary scan, 16 nodes per thread (vectorized, MLP=4).
// g_start[b] = first index i with bidx[i] >= b;  g_start[B] = N.
// ---------------------------------------------------------------------------
__global__ __launch_bounds__(256) void k_scan(
    const int* __restrict__ bidx, int N, int B)
{
    int t = blockIdx.x * 256 + threadIdx.x;
    int base = t * 16;
    if (base >= N) return;

    int v[17];
    int cnt;
    if (base + 16 <= N) {
        cnt = 16;
        int4 a = __ldg((const int4*)(bidx + base));
        int4 b = __ldg((const int4*)(bidx + base + 4));
        int4 c = __ldg((const int4*)(bidx + base + 8));
        int4 d = __ldg((const int4*)(bidx + base + 12));
        v[0]=a.x; v[1]=a.y; v[2]=a.z;  v[3]=a.w;
        v[4]=b.x; v[5]=b.y; v[6]=b.z;  v[7]=b.w;
        v[8]=c.x; v[9]=c.y; v[10]=c.z; v[11]=c.w;
        v[12]=d.x; v[13]=d.y; v[14]=d.z; v[15]=d.w;
        v[16] = (base + 16 < N) ? __ldg(bidx + base + 16) : B;
    } else {
        cnt = N - base;
        for (int j = 0; j < cnt; j++) v[j] = __ldg(bidx + base + j);
        v[cnt] = B;
    }

    if (base == 0)
        for (int b = 0; b <= v[0]; b++) g_start[b] = 0;

    #pragma unroll
    for (int j = 0; j < 16; j++) {
        if (j < cnt) {
            int cur = v[j], nx = v[j + 1];
            for (int b = cur + 1; b <= nx; b++) g_start[b] = base + j + 1;
        }
    }
}

// ---------------------------------------------------------------------------
// Kernel 1 (heterogeneous): prep blocks first (run under the pool stream):
//  blk [0,64):  W1 rows 2*blk, 2*blk+1   (W1 = Wv @ Wm_top)
//  blk 64:      g_c = bv @ Wm_top
//  blk [65, 65+B*SPLIT): exp-weighted pooling partials, 2 blocks per graph.
//    softmax is shift-invariant and gates are O(5): exp without max is safe.
// ---------------------------------------------------------------------------
__global__ __launch_bounds__(256) void k_main(
    const float* __restrict__ x,
    const float* __restrict__ Wg, const float* __restrict__ bg,
    const float* __restrict__ Wv, const float* __restrict__ Wm,
    const float* __restrict__ bv)
{
    __shared__ float sm_acc[NW][EMB];
    __shared__ float sm_d[NW];

    int blk = blockIdx.x;
    int tid = threadIdx.x;

    if (blk < 64) {
        __shared__ float av[2 * EMB];
        av[tid] = Wv[blk * (2 * EMB) + tid];
        __syncthreads();
        int j  = tid & (EMB - 1);
        int ih = tid >> 7;
        float acc = 0.f;
        #pragma unroll 16
        for (int k = 0; k < EMB; k++)
            acc += av[ih * EMB + k] * __ldg(Wm + k * EMB + j);
        g_W1[(blk * 2 + ih) * EMB + j] = acc;
        return;
    }
    if (blk == 64) {
        __shared__ float sb[EMB];
        if (tid < EMB) sb[tid] = bv[tid];
        __syncthreads();
        if (tid < EMB) {
            float acc = 0.f;
            #pragma unroll 16
            for (int k = 0; k < EMB; k++)
                acc += sb[k] * __ldg(Wm + k * EMB + tid);
            g_c[tid] = acc;
        }
        return;
    }

    int pb = blk - PREPB;
    int b  = pb >> 1;
    int s  = pb & 1;
    int start0 = g_start[b];
    int end0   = g_start[b + 1];
    int half   = (end0 - start0 + 1) >> 1;
    int start  = s ? (start0 + half) : start0;
    int end    = s ? end0 : (start0 + half);

    int lane = tid & 31;
    int w    = tid >> 5;

    float4 wg  = ((const float4*)Wg)[lane];
    float  bg0 = __ldg(bg);

    float4 acc = make_float4(0.f, 0.f, 0.f, 0.f);
    float denom = 0.f;

    for (int base = start + w * 4; base < end; base += NW * 4) {
        float4 v[4];
        float  p[4];
        bool   ok[4];
        #pragma unroll
        for (int t = 0; t < 4; t++) {
            int r = base + t;
            ok[t] = r < end;                    // warp-uniform
            v[t] = ok[t] ? __ldg(((const float4*)(x + (size_t)r * EMB)) + lane)
                         : make_float4(0.f, 0.f, 0.f, 0.f);
            p[t] = v[t].x * wg.x + v[t].y * wg.y + v[t].z * wg.z + v[t].w * wg.w;
        }
        #pragma unroll
        for (int off = 16; off; off >>= 1) {
            #pragma unroll
            for (int t = 0; t < 4; t++)
                p[t] += __shfl_xor_sync(0xffffffffu, p[t], off);
        }
        #pragma unroll
        for (int t = 0; t < 4; t++) {
            float e = ok[t] ? __expf(p[t] + bg0) : 0.f;
            acc.x += e * v[t].x; acc.y += e * v[t].y;
            acc.z += e * v[t].z; acc.w += e * v[t].w;
            denom += e;
        }
    }

    ((float4*)sm_acc[w])[lane] = acc;
    if (lane == 0) sm_d[w] = denom;
    __syncthreads();

    if (tid < EMB) {
        float sv = 0.f, d = 0.f;
        #pragma unroll
        for (int j = 0; j < NW; j++) {
            sv += sm_acc[j][tid];
            d  += sm_d[j];
        }
        g_num[(size_t)pb * EMB + tid] = sv;
        if (tid == 0) g_den[pb] = d;
    }
}

// ---------------------------------------------------------------------------
// Kernel 2: out = gp + leaky_relu( [s, gp] @ [W1; Wm_bot] + flag*c + bm )
//   s = (num0+num1)/(den0+den1)
// grid = B/GPB blocks, 512 threads. k-dim split across thread halves; float4
// weight loads (unroll 8 -> MLP 8); partials combined in smem; float4 stores.
// ---------------------------------------------------------------------------
__global__ __launch_bounds__(512) void k_out(
    const float* __restrict__ gp, const float* __restrict__ Wm,
    const float* __restrict__ bm, float* __restrict__ out)
{
    __shared__ float Ash[GPB][2 * EMB];     // [g][k]: k<128 = s, k>=128 = gp
    __shared__ float Hsh[2][GPB][EMB];      // per-half partial h
    __shared__ float Fsh[GPB];

    int gbase = blockIdx.x * GPB;
    int tid = threadIdx.x;

    for (int idx = tid; idx < GPB * EMB; idx += 512) {
        int g = idx >> 7, c = idx & 127;
        int bb = gbase + g;
        float n = g_num[(size_t)(bb * 2 + 0) * EMB + c]
                + g_num[(size_t)(bb * 2 + 1) * EMB + c];
        float d = g_den[bb * 2] + g_den[bb * 2 + 1];
        Ash[g][c]       = (d > 0.f) ? (n / d) : 0.f;
        Ash[g][EMB + c] = __ldg(gp + (size_t)bb * EMB + c);
        if (c == 0) Fsh[g] = (d > 0.f) ? 1.f : 0.f;
    }
    __syncthreads();

    {
        int h  = tid >> 8;                  // 0: W1/s half, 1: Wm_bot/gp half
        int g  = (tid >> 5) & 7;
        int j4 = tid & 31;

        const float* W = h ? (Wm + EMB * EMB) : g_W1;
        const float* A = Ash[g] + h * EMB;

        float4 acc = make_float4(0.f, 0.f, 0.f, 0.f);
        #pragma unroll 8
        for (int k = 0; k < EMB; k++) {
            float4 wv = __ldg(((const float4*)(W + (size_t)k * EMB)) + j4);
            float  a  = A[k];
            acc.x += a * wv.x; acc.y += a * wv.y;
            acc.z += a * wv.z; acc.w += a * wv.w;
        }
        ((float4*)Hsh[h][g])[j4] = acc;
    }
    __syncthreads();

    if (tid < 256) {
        int g  = tid >> 5;
        int j4 = tid & 31;
        float4 h0 = ((const float4*)Hsh[0][g])[j4];
        float4 h1 = ((const float4*)Hsh[1][g])[j4];
        float4 c4 = ((const float4*)g_c)[j4];
        float4 b4 = __ldg(((const float4*)bm) + j4);
        float4 r4 = ((const float4*)(Ash[g] + EMB))[j4];
        float fl = Fsh[g];

        float4 o;
        float hh;
        hh = h0.x + h1.x + fl * c4.x + b4.x; o.x = r4.x + (hh > 0.f ? hh : 0.01f * hh);
        hh = h0.y + h1.y + fl * c4.y + b4.y; o.y = r4.y + (hh > 0.f ? hh : 0.01f * hh);
        hh = h0.z + h1.z + fl * c4.z + b4.z; o.z = r4.z + (hh > 0.f ? hh : 0.01f * hh);
        hh = h0.w + h1.w + fl * c4.w + b4.w; o.w = r4.w + (hh > 0.f ? hh : 0.01f * hh);

        ((float4*)(out + (size_t)(gbase + g) * EMB))[j4] = o;
    }
}

extern "C" void kernel_launch(void* const* d_in, const int* in_sizes, int n_in,
                              void* d_out, int out_size)
{
    const float* x    = (const float*)d_in[0];
    const float* gp   = (const float*)d_in[1];
    const int*   bidx = (const int*)  d_in[2];
    const float* Wg   = (const float*)d_in[3];
    const float* bg   = (const float*)d_in[4];
    const float* Wv   = (const float*)d_in[5];
    const float* bv   = (const float*)d_in[6];
    const float* Wm   = (const float*)d_in[7];
    const float* bm   = (const float*)d_in[8];
    float* out = (float*)d_out;

    int N = in_sizes[0] / EMB;
    int B = in_sizes[1] / EMB;

    int scan_threads = (N + 15) / 16;
    int scan_grid = (scan_threads + 255) / 256;
    k_scan<<<scan_grid, 256>>>(bidx, N, B);
    k_main<<<PREPB + B * SPLIT, 256>>>(x, Wg, bg, Wv, Wm, bv);
    k_out<<<B / GPB, 512>>>(gp, Wm, bm, out);
}